// round 10
// baseline (speedup 1.0000x reference)
#include <cuda_runtime.h>
#include <cuda_bf16.h>

#define BATCH 512
#define TLEN  256
#define HID   512
#define HALF  256
#define TGT   28

#define NTHREADS 256
#define NCTAS 256
#define GSZ (NCTAS * NTHREADS)
#define WSMEM_BYTES 32768   // 16 kt32 x 4 n8 x 512B (hi+lo int8 W fragments)

#define SH 32256.0f          // h scale (|h|<1 -> |h_q|<=32256, no clamp needed)
#define SW 65536.0f          // w scale (|w|<0.49 assumed; clamped)
#define C1 (1.0f / 32256.0f)            // acc1 * 2^16 / (SH*SW)
#define C2 (1.0f / 8257536.0f)          // acc2 * 2^8  / (SH*SW)

// ---------------- device scratch ----------------
// A(h) chunk per (m16,kt32): 1KB = [hi plane 512B: lane*16][lo plane: +512]
__device__ __align__(16) unsigned char g_hfrag[2][1 << 20];
// B(W) chunk per (n8,kt32): 512B = lane*16 : {b0_hi, b1_hi, b0_lo, b1_lo}
__device__ __align__(16) unsigned char g_Wfrag[2 << 20];
__device__ __align__(16) float g_hfin[BATCH * HID];
__device__ unsigned int g_barcnt0;
__device__ volatile unsigned int g_bargen0;
__device__ unsigned int g_aflag[4][512];      // flag per (grp, tileN): slot tileN*8 (32B apart)
__device__ unsigned int g_rel[4 * 32];        // release flag per group (128B apart)

// full-grid barrier (prep only)
__device__ __forceinline__ void gridbar0() {
    __threadfence();
    __syncthreads();
    if (threadIdx.x == 0) {
        unsigned int gen = g_bargen0;
        if (atomicAdd(&g_barcnt0, 1u) == NCTAS - 1u) {
            g_barcnt0 = 0u;
            __threadfence();
            g_bargen0 = gen + 1u;
        } else {
            while (g_bargen0 == gen) { }
            __threadfence();
        }
    }
    __syncthreads();
}

// 64-CTA group barrier, flag-array (no atomic serialization); ep strictly increasing
__device__ __forceinline__ void groupbar(int grp, int tileN, unsigned int ep,
                                         int wti, int lane) {
    __threadfence();               // release h-fragment STGs
    __syncthreads();
    if (wti == 0) {
        if (lane == 0)
            *(volatile unsigned int*)&g_aflag[grp][tileN * 8] = ep;
        if (tileN == 0) {          // checker CTA: one warp watches all 64 flags
            volatile unsigned int* f0 = &g_aflag[grp][lane * 8];
            volatile unsigned int* f1 = &g_aflag[grp][(lane + 32) * 8];
            while (__any_sync(0xffffffffu, (*f0 < ep) || (*f1 < ep))) { }
            if (lane == 0)
                *(volatile unsigned int*)&g_rel[grp * 32] = ep;
        }
        if (lane == 0) {
            while (*(volatile unsigned int*)&g_rel[grp * 32] < ep) { }
            __threadfence();       // acquire + CCTL.IVALL (L1 safe for plain LDG)
        }
    }
    __syncthreads();
}

__device__ __forceinline__ float sigf(float x)  { return 1.0f / (1.0f + __expf(-x)); }
__device__ __forceinline__ float tanhft(float x){ return 1.0f - 2.0f / (__expf(2.0f * x) + 1.0f); }

__device__ __forceinline__ unsigned int pack4b(int b0, int b1, int b2, int b3) {
    return (unsigned int)(b0 & 255) | ((unsigned int)(b1 & 255) << 8) |
           ((unsigned int)(b2 & 255) << 16) | ((unsigned int)(b3 & 255) << 24);
}

#define MMA_S8(c, A, B0, B1)                                                \
    asm volatile("mma.sync.aligned.m16n8k32.row.col.s32.s8.s8.s32 "         \
                 "{%0,%1,%2,%3}, {%4,%5,%6,%7}, {%8,%9}, {%0,%1,%2,%3};"    \
                 : "+r"(c[0]), "+r"(c[1]), "+r"(c[2]), "+r"(c[3])           \
                 : "r"(A.x), "r"(A.y), "r"(A.z), "r"(A.w), "r"(B0), "r"(B1))

__global__ __launch_bounds__(NTHREADS, 2)
void lstm_mma_kernel(
    const float* __restrict__ seq,  const float* __restrict__ W_ih,
    const float* __restrict__ W_hh, const float* __restrict__ b_ih,
    const float* __restrict__ b_hh, const float* __restrict__ fc1w,
    const float* __restrict__ fc1b, const float* __restrict__ fc2w,
    const float* __restrict__ fc2b, float* __restrict__ out)
{
    extern __shared__ unsigned char wsm[];                 // 32KB W fragments
    __shared__ __align__(16) float stage[8][16][8];        // per-warp h tile (fp32)
    __shared__ __align__(16) float4 sm_wih[8], sm_bias[8];
    __shared__ __align__(16) float hs[2][HID];             // fc1 input rows
    __shared__ __align__(16) float sm_hid[2][HALF];        // fc1 output rows

    const int tid  = threadIdx.x;
    const int cta  = blockIdx.x;
    const int gid  = cta * NTHREADS + tid;
    const int lane = tid & 31;
    const int wti  = tid >> 5;
    const int gq   = lane >> 2;
    const int tg   = lane & 3;

    // ---- prep: W int8 dual-plane fragments (gate-interleave reorder) ----
    // gate-col n: w16=n&15, gate=((w16>>3)<<1)|(w16&1), unit=(n>>4)*4+((w16&7)>>1)
    for (int it = gid; it < 256 * 16 * 32; it += GSZ) {
        int ln  = it & 31;
        int kt  = (it >> 5) & 15;
        int n8  = it >> 9;
        int n   = n8 * 8 + (ln >> 2);
        int w16 = n & 15;
        int gate = ((w16 >> 3) << 1) | (w16 & 1);
        int unit = (n >> 4) * 4 + ((w16 & 7) >> 1);
        const float* wr = W_hh + (gate * HID + unit) * HID + kt * 32 + ((ln & 3) << 2);
        float4 w0 = *(const float4*)wr;          // k = base..base+3
        float4 w1 = *(const float4*)(wr + 16);   // k = base+16..base+19
        int q[8], hi[8], lo[8];
        float wv[8] = { w0.x, w0.y, w0.z, w0.w, w1.x, w1.y, w1.z, w1.w };
        #pragma unroll
        for (int i = 0; i < 8; ++i) {
            int qq = __float2int_rn(wv[i] * SW);
            qq = max(-32511, min(32511, qq));
            q[i] = qq;
            hi[i] = (qq + 128) >> 8;
            lo[i] = qq - (hi[i] << 8);
        }
        uint4 v;
        v.x = pack4b(hi[0], hi[1], hi[2], hi[3]);   // b0 hi
        v.y = pack4b(hi[4], hi[5], hi[6], hi[7]);   // b1 hi
        v.z = pack4b(lo[0], lo[1], lo[2], lo[3]);   // b0 lo
        v.w = pack4b(lo[4], lo[5], lo[6], lo[7]);   // b1 lo
        *(uint4*)(g_Wfrag + (((n8 << 4) + kt) << 9) + ln * 16) = v;
    }
    {   // zero h fragments buffer 0 (h = 0 -> planes all zero)
        uint4 z = make_uint4(0, 0, 0, 0);
        uint4* hz = (uint4*)g_hfrag[0];
        for (int e = gid; e < (1 << 16); e += GSZ) hz[e] = z;
    }
    gridbar0();

    // ---- per-CTA geometry ----
    const int tileM = cta & 3;             // co-resident CTAs share tileM
    const int tileN = cta >> 2;            // 0..63 (32 gate-cols = 8 units)
    const int m16g  = tileM * 8 + wti;

    // copy this CTA's W fragments to smem (once; chunks (kt*4+j))
    {
        uint4* s4 = (uint4*)wsm;
        const uint4* g4 = (const uint4*)g_Wfrag;
        for (int e = tid; e < WSMEM_BYTES / 16; e += NTHREADS) {
            int w = e & 31, c = e >> 5;
            int kt = c >> 2, j = c & 3;
            s4[e] = __ldcg(&g4[((((tileN * 4 + j) << 4) + kt) << 5) + w]);
        }
    }
    for (int e = tid; e < 32; e += NTHREADS) {
        int u = e >> 2, g = e & 3;
        int ku = tileN * 8 + u;
        ((float*)sm_wih)[e]  = W_ih[g * HID + ku];
        ((float*)sm_bias)[e] = b_ih[g * HID + ku] + b_hh[g * HID + ku];
    }
    __syncthreads();

    float creg[2][2];                      // [rh][block b]
    creg[0][0] = creg[0][1] = creg[1][0] = creg[1][1] = 0.0f;

    const int row_base = tileM * 128 + wti * 16 + gq;
    const int ktw = tileN >> 2;            // A-chunk this CTA co-writes
    const int ko  = (tileN & 3) * 8;       // k-col offset within that chunk

    // ---- recurrent loop ----
    for (int t = 0; t < TLEN; ++t) {
        const unsigned char* hin  = g_hfrag[t & 1];
        unsigned char*       hout = g_hfrag[(t + 1) & 1];
        const unsigned char* abase = hin + ((size_t)(m16g * 16) << 10) + lane * 16;
        const unsigned char* wbase = wsm + lane * 16;

        int acc1[4][4], acc2[4][4];
        #pragma unroll
        for (int j = 0; j < 4; ++j)
            #pragma unroll
            for (int c = 0; c < 4; ++c) { acc1[j][c] = 0; acc2[j][c] = 0; }

        uint4 ah[2], al[2];                // plain LDG -> L1 (fence invalidates)
        ah[0] = *(const uint4*)(abase);
        al[0] = *(const uint4*)(abase + 512);
        ah[1] = *(const uint4*)(abase + 1024);
        al[1] = *(const uint4*)(abase + 1536);

        #pragma unroll 2
        for (int kt = 0; kt < 16; ++kt) {
            const int s = kt & 1;
            uint4 bw[4];
            #pragma unroll
            for (int j = 0; j < 4; ++j)
                bw[j] = *(const uint4*)(wbase + (((kt << 2) + j) << 9));
            #pragma unroll
            for (int j = 0; j < 4; ++j) MMA_S8(acc1[j], ah[s], bw[j].x, bw[j].y); // hh*wh
            #pragma unroll
            for (int j = 0; j < 4; ++j) MMA_S8(acc2[j], al[s], bw[j].x, bw[j].y); // hl*wh
            #pragma unroll
            for (int j = 0; j < 4; ++j) MMA_S8(acc2[j], ah[s], bw[j].z, bw[j].w); // hh*wl
            if (kt + 2 < 16) {
                const unsigned char* p = abase + ((size_t)(kt + 2) << 10);
                ah[s] = *(const uint4*)p;
                al[s] = *(const uint4*)(p + 512);
            }
        }

        // ---- epilogue: gates -> c,h ; stage h (fp32) ----
        #pragma unroll
        for (int rh = 0; rh < 2; ++rh) {
            float xv = seq[(row_base + rh * 8) * TLEN + t];
            #pragma unroll
            for (int b = 0; b < 2; ++b) {
                float4 wv = sm_wih[b * 4 + tg];
                float4 bv = sm_bias[b * 4 + tg];
                int i0 = rh * 2, i1 = rh * 2 + 1;
                float gi = (float)acc1[2*b  ][i0] * C1 + (float)acc2[2*b  ][i0] * C2 + xv * wv.x + bv.x;
                float gf = (float)acc1[2*b  ][i1] * C1 + (float)acc2[2*b  ][i1] * C2 + xv * wv.y + bv.y;
                float gg = (float)acc1[2*b+1][i0] * C1 + (float)acc2[2*b+1][i0] * C2 + xv * wv.z + bv.z;
                float go = (float)acc1[2*b+1][i1] * C1 + (float)acc2[2*b+1][i1] * C2 + xv * wv.w + bv.w;
                float cc = sigf(gf) * creg[rh][b] + sigf(gi) * tanhft(gg);
                creg[rh][b] = cc;
                float hv = sigf(go) * tanhft(cc);
                stage[wti][gq + rh * 8][b * 4 + tg] = hv;
                if (t == TLEN - 1)
                    g_hfin[(row_base + rh * 8) * HID + tileN * 8 + b * 4 + tg] = hv;
            }
        }
        __syncwarp();
        // repack: thread -> one (row16, kq) position; quantize 4 h to hi/lo planes
        {
            int row16 = gq + ((tg >> 1) << 3);
            int kq    = tg & 1;
            int k_local = ko + kq * 4;
            int reg   = ((row16 >> 3)) + ((k_local >> 4) << 1);
            int lane_c = (row16 & 7) * 4 + ((k_local & 15) >> 2);
            const float* sp = &stage[wti][row16][kq * 4];
            int hi[4], lo[4];
            #pragma unroll
            for (int i = 0; i < 4; ++i) {
                int q = __float2int_rn(sp[i] * SH);
                hi[i] = (q + 128) >> 8;
                lo[i] = q - (hi[i] << 8);
            }
            unsigned char* base = hout + ((size_t)(m16g * 16 + ktw) << 10)
                                       + lane_c * 16 + reg * 4;
            *(unsigned int*)base         = pack4b(hi[0], hi[1], hi[2], hi[3]);
            *(unsigned int*)(base + 512) = pack4b(lo[0], lo[1], lo[2], lo[3]);
        }

        groupbar(tileM, tileN, (unsigned int)(t + 1), wti, lane);
    }

    // ---- fc1: hid = relu(h @ fc1w^T + fc1b), 2 batch rows per CTA ----
    const int bb = tileM * 128 + tileN * 2;
    {
        for (int e = tid; e < 2 * HID; e += NTHREADS)
            hs[e >> 9][e & 511] = g_hfin[(bb + (e >> 9)) * HID + (e & 511)];
        __syncthreads();
        int n = tid;                            // HALF == 256 == NTHREADS
        const float* wr = fc1w + n * HID;
        float s0 = fc1b[n], s1 = s0;
        #pragma unroll 8
        for (int k = 0; k < HID; ++k) {
            float w = wr[k];
            s0 += hs[0][k] * w; s1 += hs[1][k] * w;
        }
        sm_hid[0][n] = fmaxf(s0, 0.0f);
        sm_hid[1][n] = fmaxf(s1, 0.0f);
    }
    __syncthreads();

    // ---- fc2 (rows bb, bb+1) ----
    for (int i = tid; i < 2 * TGT; i += NTHREADS) {
        int r  = i / TGT;
        int tt = i - r * TGT;
        const float* hr = sm_hid[r];
        const float* wr = fc2w + tt * HALF;
        float s = fc2b[tt];
        #pragma unroll 8
        for (int k = 0; k < HALF; ++k) s += hr[k] * wr[k];
        out[(bb + r) * TGT + tt] = s;
    }
}

extern "C" void kernel_launch(void* const* d_in, const int* in_sizes, int n_in,
                              void* d_out, int out_size) {
    (void)in_sizes; (void)n_in; (void)out_size;
    cudaFuncSetAttribute(lstm_mma_kernel,
                         cudaFuncAttributeMaxDynamicSharedMemorySize, WSMEM_BYTES);
    lstm_mma_kernel<<<NCTAS, NTHREADS, WSMEM_BYTES>>>(
        (const float*)d_in[0], (const float*)d_in[1], (const float*)d_in[2],
        (const float*)d_in[3], (const float*)d_in[4], (const float*)d_in[5],
        (const float*)d_in[6], (const float*)d_in[7], (const float*)d_in[8],
        (float*)d_out);
}

// round 11
// speedup vs baseline: 2.6687x; 2.6687x over previous
#include <cuda_runtime.h>
#include <cuda_fp16.h>

#define BATCH 512
#define TLEN  256
#define HID   512
#define HALF  256
#define TGT   28

#define NTHREADS 256
#define NCTAS 256
#define GSZ (NCTAS * NTHREADS)
#define WSMEM_BYTES 32768   // 32 k16 x 4 n8 x 256B (single-plane fp16 W fragments)

// ---------------- device scratch ----------------
// A(h) chunk per (m16,k16): 1KB = [hi plane 512B: lane*16][lo plane: +512]
__device__ __align__(16) unsigned char g_hfrag[2][1 << 20];
// B(W) chunk per (n8,k16): 256B = lane*8 : {b0, b1} fp16x2
__device__ __align__(16) unsigned char g_Wfrag[2 << 20];
__device__ __align__(16) float g_hfin[BATCH * HID];
__device__ unsigned int g_barcnt0;
__device__ volatile unsigned int g_bargen0;
__device__ unsigned int g_aflag[4][512];      // flag per (grp,tileN): slot tileN*8 (32B apart)
__device__ unsigned int g_rel[4 * 32];        // release flag per group (128B apart)

// full-grid barrier (sense-reversing; replay-safe)
__device__ __forceinline__ void gridbar0() {
    __threadfence();
    __syncthreads();
    if (threadIdx.x == 0) {
        unsigned int gen = g_bargen0;
        if (atomicAdd(&g_barcnt0, 1u) == NCTAS - 1u) {
            g_barcnt0 = 0u;
            __threadfence();
            g_bargen0 = gen + 1u;
        } else {
            while (g_bargen0 == gen) { }
            __threadfence();
        }
    }
    __syncthreads();
}

// 64-CTA group barrier, flag-array; ep strictly increasing within a launch.
// Flags are reset to 0 at end of kernel (cross-launch safety).
__device__ __forceinline__ void groupbar(int grp, int tileN, unsigned int ep,
                                         int wti, int lane) {
    __threadfence();               // release h-fragment STGs
    __syncthreads();
    if (wti == 0) {
        if (lane == 0)
            *(volatile unsigned int*)&g_aflag[grp][tileN * 8] = ep;
        if (tileN == 0) {          // checker CTA: one warp watches all 64 flags
            volatile unsigned int* f0 = &g_aflag[grp][lane * 8];
            volatile unsigned int* f1 = &g_aflag[grp][(lane + 32) * 8];
            while (__any_sync(0xffffffffu, (*f0 < ep) || (*f1 < ep))) { }
            if (lane == 0)
                *(volatile unsigned int*)&g_rel[grp * 32] = ep;
        }
        if (lane == 0) {
            while (*(volatile unsigned int*)&g_rel[grp * 32] < ep) { }
            __threadfence();       // acquire + CCTL.IVALL (L1 safe for plain LDG)
        }
    }
    __syncthreads();
}

__device__ __forceinline__ float sigf(float x)  { return 1.0f / (1.0f + __expf(-x)); }
__device__ __forceinline__ float tanhft(float x){ return 1.0f - 2.0f / (__expf(2.0f * x) + 1.0f); }

__device__ __forceinline__ unsigned int packh(float a, float b) {
    __half2 h = __floats2half2_rn(a, b);
    return reinterpret_cast<unsigned int&>(h);
}

#define MMA_F16(c, A, B0, B1)                                               \
    asm volatile("mma.sync.aligned.m16n8k16.row.col.f32.f16.f16.f32 "       \
                 "{%0,%1,%2,%3}, {%4,%5,%6,%7}, {%8,%9}, {%0,%1,%2,%3};"    \
                 : "+f"(c[0]), "+f"(c[1]), "+f"(c[2]), "+f"(c[3])           \
                 : "r"(A.x), "r"(A.y), "r"(A.z), "r"(A.w), "r"(B0), "r"(B1))

__global__ __launch_bounds__(NTHREADS, 2)
void lstm_mma_kernel(
    const float* __restrict__ seq,  const float* __restrict__ W_ih,
    const float* __restrict__ W_hh, const float* __restrict__ b_ih,
    const float* __restrict__ b_hh, const float* __restrict__ fc1w,
    const float* __restrict__ fc1b, const float* __restrict__ fc2w,
    const float* __restrict__ fc2b, float* __restrict__ out)
{
    extern __shared__ unsigned char wsm[];                 // 32KB W fragments
    __shared__ __align__(16) float stage[8][16][8];        // per-warp h tile (fp32)
    __shared__ __align__(16) float4 sm_wih[8], sm_bias[8];
    __shared__ __align__(16) float hs[2][HID];             // fc1 input rows
    __shared__ __align__(16) float sm_hid[2][HALF];        // fc1 output rows

    const int tid  = threadIdx.x;
    const int cta  = blockIdx.x;
    const int gid  = cta * NTHREADS + tid;
    const int lane = tid & 31;
    const int wti  = tid >> 5;
    const int gq   = lane >> 2;
    const int tg   = lane & 3;

    // ---- prep: W fp16 fragments (gate-interleave reorder). col n:
    // w16=n&15, gate=((w16>>3)<<1)|(w16&1), unit=(n>>4)*4+((w16&7)>>1)
    for (int it = gid; it < 256 * 32 * 32; it += GSZ) {
        int ln  = it & 31;
        int k16 = (it >> 5) & 31;
        int n8  = it >> 10;
        int n   = n8 * 8 + (ln >> 2);
        int w16 = n & 15;
        int gate = ((w16 >> 3) << 1) | (w16 & 1);
        int unit = (n >> 4) * 4 + ((w16 & 7) >> 1);
        const float* wr = W_hh + (gate * HID + unit) * HID + k16 * 16 + ((ln & 3) << 1);
        float2 p0 = *(const float2*)wr;          // k, k+1
        float2 p1 = *(const float2*)(wr + 8);    // k+8, k+9
        uint2 v;
        v.x = packh(p0.x, p0.y);
        v.y = packh(p1.x, p1.y);
        *(uint2*)(g_Wfrag + (((n8 << 5) + k16) << 8) + ln * 8) = v;
    }
    {   // zero h fragments buffer 0 (h = 0)
        uint4 z = make_uint4(0, 0, 0, 0);
        uint4* hz = (uint4*)g_hfrag[0];
        for (int e = gid; e < (1 << 16); e += GSZ) hz[e] = z;
    }
    gridbar0();

    // ---- per-CTA geometry ----
    const int tileM = cta & 3;             // co-resident CTAs share tileM
    const int tileN = cta >> 2;            // 0..63 (32 gate-cols = 8 units)
    const int m16g  = tileM * 8 + wti;

    // copy this CTA's W fragments to smem (once; chunks (kt*4+j), 256B each)
    {
        uint4* s4 = (uint4*)wsm;
        const uint4* g4 = (const uint4*)g_Wfrag;
        for (int e = tid; e < WSMEM_BYTES / 16; e += NTHREADS) {
            int w = e & 15, c = e >> 4;
            int kt = c >> 2, j = c & 3;
            s4[e] = __ldcg(&g4[((((tileN * 4 + j) << 5) + kt) << 4) + w]);
        }
    }
    for (int e = tid; e < 32; e += NTHREADS) {
        int u = e >> 2, g = e & 3;
        int ku = tileN * 8 + u;
        ((float*)sm_wih)[e]  = W_ih[g * HID + ku];
        ((float*)sm_bias)[e] = b_ih[g * HID + ku] + b_hh[g * HID + ku];
    }
    __syncthreads();

    float creg[2][2];                      // [rh][block b]
    creg[0][0] = creg[0][1] = creg[1][0] = creg[1][1] = 0.0f;

    const int row_base = tileM * 128 + wti * 16 + gq;
    const int k16w = tileN >> 1;           // A-fragment k16 this CTA co-writes
    const int khalf = tileN & 1;           // which 8-byte half of each lane slot

    // ---- recurrent loop ----
    for (int t = 0; t < TLEN; ++t) {
        const unsigned char* hin  = g_hfrag[t & 1];
        unsigned char*       hout = g_hfrag[(t + 1) & 1];
        const unsigned char* abase = hin + ((size_t)(m16g * 32) << 10) + lane * 16;
        const unsigned char* wbase = wsm + lane * 8;

        float acc[4][4];
        #pragma unroll
        for (int j = 0; j < 4; ++j)
            #pragma unroll
            for (int c = 0; c < 4; ++c) acc[j][c] = 0.0f;

        uint4 ah[2], al[2];                // plain LDG -> L1 (fence invalidates)
        ah[0] = *(const uint4*)(abase);
        al[0] = *(const uint4*)(abase + 512);
        ah[1] = *(const uint4*)(abase + 1024);
        al[1] = *(const uint4*)(abase + 1536);

        #pragma unroll 2
        for (int kt = 0; kt < 32; ++kt) {
            const int s = kt & 1;
            uint2 bw[4];
            #pragma unroll
            for (int j = 0; j < 4; ++j)
                bw[j] = *(const uint2*)(wbase + (((kt << 2) + j) << 8));
            #pragma unroll
            for (int j = 0; j < 4; ++j) MMA_F16(acc[j], ah[s], bw[j].x, bw[j].y); // h_hi*w
            #pragma unroll
            for (int j = 0; j < 4; ++j) MMA_F16(acc[j], al[s], bw[j].x, bw[j].y); // h_lo*w
            if (kt + 2 < 32) {
                const unsigned char* p = abase + ((size_t)(kt + 2) << 10);
                ah[s] = *(const uint4*)p;
                al[s] = *(const uint4*)(p + 512);
            }
        }

        // ---- epilogue: gates -> c,h ; stage h (fp32) ----
        #pragma unroll
        for (int rh = 0; rh < 2; ++rh) {
            float xv = seq[(row_base + rh * 8) * TLEN + t];
            #pragma unroll
            for (int b = 0; b < 2; ++b) {
                float4 wv = sm_wih[b * 4 + tg];
                float4 bv = sm_bias[b * 4 + tg];
                float gi = acc[2*b  ][rh*2+0] + xv * wv.x + bv.x;
                float gf = acc[2*b  ][rh*2+1] + xv * wv.y + bv.y;
                float gg = acc[2*b+1][rh*2+0] + xv * wv.z + bv.z;
                float go = acc[2*b+1][rh*2+1] + xv * wv.w + bv.w;
                float cc = sigf(gf) * creg[rh][b] + sigf(gi) * tanhft(gg);
                creg[rh][b] = cc;
                float hv = sigf(go) * tanhft(cc);
                stage[wti][gq + rh * 8][b * 4 + tg] = hv;
                if (t == TLEN - 1)
                    g_hfin[(row_base + rh * 8) * HID + tileN * 8 + b * 4 + tg] = hv;
            }
        }
        __syncwarp();
        // repack: this CTA supplies k-half 'khalf' of A fragment (m16g, k16w)
        {
            float a0 = stage[wti][gq    ][tg * 2];
            float a1 = stage[wti][gq    ][tg * 2 + 1];
            float b0 = stage[wti][gq + 8][tg * 2];
            float b1 = stage[wti][gq + 8][tg * 2 + 1];
            __half a0h = __float2half_rn(a0), a1h = __float2half_rn(a1);
            __half b0h = __float2half_rn(b0), b1h = __float2half_rn(b1);
            unsigned int hi0 = packh(a0, a1), hi1 = packh(b0, b1);
            unsigned int lo0 = packh(a0 - __half2float(a0h), a1 - __half2float(a1h));
            unsigned int lo1 = packh(b0 - __half2float(b0h), b1 - __half2float(b1h));
            unsigned char* op = hout + ((size_t)(m16g * 32 + k16w) << 10)
                                     + lane * 16 + khalf * 8;
            *(uint2*)op         = make_uint2(hi0, hi1);
            *(uint2*)(op + 512) = make_uint2(lo0, lo1);
        }

        groupbar(tileM, tileN, (unsigned int)(t + 1), wti, lane);
    }

    // ---- reset barrier flags for next graph replay (after full-grid sync) ----
    gridbar0();
    if (tid == 0) {
        *(volatile unsigned int*)&g_aflag[tileM][tileN * 8] = 0u;
        if (tileN == 0)
            *(volatile unsigned int*)&g_rel[tileM * 32] = 0u;
    }

    // ---- fc1: hid = relu(h @ fc1w^T + fc1b), 2 batch rows per CTA ----
    const int bb = tileM * 128 + tileN * 2;
    {
        for (int e = tid; e < 2 * HID; e += NTHREADS)
            hs[e >> 9][e & 511] = g_hfin[(bb + (e >> 9)) * HID + (e & 511)];
        __syncthreads();
        int n = tid;                            // HALF == 256 == NTHREADS
        const float* wr = fc1w + n * HID;
        float s0 = fc1b[n], s1 = s0;
        #pragma unroll 8
        for (int k = 0; k < HID; ++k) {
            float w = wr[k];
            s0 += hs[0][k] * w; s1 += hs[1][k] * w;
        }
        sm_hid[0][n] = fmaxf(s0, 0.0f);
        sm_hid[1][n] = fmaxf(s1, 0.0f);
    }
    __syncthreads();

    // ---- fc2 (rows bb, bb+1) ----
    for (int i = tid; i < 2 * TGT; i += NTHREADS) {
        int r  = i / TGT;
        int tt = i - r * TGT;
        const float* hr = sm_hid[r];
        const float* wr = fc2w + tt * HALF;
        float s = fc2b[tt];
        #pragma unroll 8
        for (int k = 0; k < HALF; ++k) s += hr[k] * wr[k];
        out[(bb + r) * TGT + tt] = s;
    }
}

extern "C" void kernel_launch(void* const* d_in, const int* in_sizes, int n_in,
                              void* d_out, int out_size) {
    (void)in_sizes; (void)n_in; (void)out_size;
    cudaFuncSetAttribute(lstm_mma_kernel,
                         cudaFuncAttributeMaxDynamicSharedMemorySize, WSMEM_BYTES);
    lstm_mma_kernel<<<NCTAS, NTHREADS, WSMEM_BYTES>>>(
        (const float*)d_in[0], (const float*)d_in[1], (const float*)d_in[2],
        (const float*)d_in[3], (const float*)d_in[4], (const float*)d_in[5],
        (const float*)d_in[6], (const float*)d_in[7], (const float*)d_in[8],
        (float*)d_out);
}

// round 12
// speedup vs baseline: 2.8549x; 1.0698x over previous
#include <cuda_runtime.h>
#include <cuda_fp16.h>

#define BATCH 512
#define TLEN  256
#define HID   512
#define HALF  256
#define TGT   28

#define NTHREADS 256
#define NCTAS 256
#define GSZ (NCTAS * NTHREADS)
#define WSMEM_BYTES 32768   // 32 k16 x 4 n8 x 256B (fp16 W fragments)

// ---------------- device scratch ----------------
// A(h) fragment per (m16,k16): 512B = lane*16 (4 .f16x2 regs)
__device__ __align__(16) unsigned char g_hfrag[2][1 << 19];
// B(W) fragment per (n8,k16): 256B = lane*8 : {b0, b1} fp16x2
__device__ __align__(16) unsigned char g_Wfrag[2 << 20];
__device__ __align__(16) float g_hfin[BATCH * HID];
__device__ unsigned int g_barcnt0;
__device__ volatile unsigned int g_bargen0;
__device__ unsigned int g_aflag[4][512];      // flag per (grp,tileN): slot tileN*8 (32B apart)

// full-grid barrier (sense-reversing; replay-safe)
__device__ __forceinline__ void gridbar0() {
    __threadfence();
    __syncthreads();
    if (threadIdx.x == 0) {
        unsigned int gen = g_bargen0;
        if (atomicAdd(&g_barcnt0, 1u) == NCTAS - 1u) {
            g_barcnt0 = 0u;
            __threadfence();
            g_bargen0 = gen + 1u;
        } else {
            while (g_bargen0 == gen) { }
            __threadfence();
        }
    }
    __syncthreads();
}

// 64-CTA group barrier, one-hop flag-array: every CTA's warp0 polls all 64 flags.
// ep strictly increasing within a launch; flags reset before fc tail.
__device__ __forceinline__ void groupbar(int grp, int tileN, unsigned int ep,
                                         int wti, int lane) {
    __threadfence();               // release h-fragment STGs
    __syncthreads();
    if (wti == 0) {
        if (lane == 0)
            *(volatile unsigned int*)&g_aflag[grp][tileN * 8] = ep;
        volatile unsigned int* f0 = &g_aflag[grp][lane * 8];
        volatile unsigned int* f1 = &g_aflag[grp][(lane + 32) * 8];
        while (__any_sync(0xffffffffu, (*f0 < ep) || (*f1 < ep))) { }
        if (lane == 0)
            __threadfence();       // acquire + CCTL.IVALL (L1 safe for plain LDG)
    }
    __syncthreads();
}

__device__ __forceinline__ float sigf(float x)  { return 1.0f / (1.0f + __expf(-x)); }
__device__ __forceinline__ float tanhft(float x){ return 1.0f - 2.0f / (__expf(2.0f * x) + 1.0f); }

__device__ __forceinline__ unsigned int packh(float a, float b) {
    __half2 h = __floats2half2_rn(a, b);
    return reinterpret_cast<unsigned int&>(h);
}

#define MMA_F16(c, A, B0, B1)                                               \
    asm volatile("mma.sync.aligned.m16n8k16.row.col.f32.f16.f16.f32 "       \
                 "{%0,%1,%2,%3}, {%4,%5,%6,%7}, {%8,%9}, {%0,%1,%2,%3};"    \
                 : "+f"(c[0]), "+f"(c[1]), "+f"(c[2]), "+f"(c[3])           \
                 : "r"(A.x), "r"(A.y), "r"(A.z), "r"(A.w), "r"(B0), "r"(B1))

__global__ __launch_bounds__(NTHREADS, 2)
void lstm_mma_kernel(
    const float* __restrict__ seq,  const float* __restrict__ W_ih,
    const float* __restrict__ W_hh, const float* __restrict__ b_ih,
    const float* __restrict__ b_hh, const float* __restrict__ fc1w,
    const float* __restrict__ fc1b, const float* __restrict__ fc2w,
    const float* __restrict__ fc2b, float* __restrict__ out)
{
    extern __shared__ unsigned char wsm[];                 // 32KB W fragments
    __shared__ __align__(16) float stage[8][16][8];        // per-warp h tile (fp32)
    __shared__ __align__(16) float4 sm_wih[8], sm_bias[8];
    __shared__ __align__(16) float hs[2][HID];             // fc1 input rows
    __shared__ __align__(16) float sm_hid[2][HALF];        // fc1 output rows

    const int tid  = threadIdx.x;
    const int cta  = blockIdx.x;
    const int gid  = cta * NTHREADS + tid;
    const int lane = tid & 31;
    const int wti  = tid >> 5;
    const int gq   = lane >> 2;
    const int tg   = lane & 3;

    // ---- prep: W fp16 fragments (gate-interleave reorder). col n:
    // w16=n&15, gate=((w16>>3)<<1)|(w16&1), unit=(n>>4)*4+((w16&7)>>1)
    for (int it = gid; it < 256 * 32 * 32; it += GSZ) {
        int ln  = it & 31;
        int k16 = (it >> 5) & 31;
        int n8  = it >> 10;
        int n   = n8 * 8 + (ln >> 2);
        int w16 = n & 15;
        int gate = ((w16 >> 3) << 1) | (w16 & 1);
        int unit = (n >> 4) * 4 + ((w16 & 7) >> 1);
        const float* wr = W_hh + (gate * HID + unit) * HID + k16 * 16 + ((ln & 3) << 1);
        float2 p0 = *(const float2*)wr;          // k, k+1
        float2 p1 = *(const float2*)(wr + 8);    // k+8, k+9
        uint2 v;
        v.x = packh(p0.x, p0.y);
        v.y = packh(p1.x, p1.y);
        *(uint2*)(g_Wfrag + (((n8 << 5) + k16) << 8) + ln * 8) = v;
    }
    {   // zero h fragments buffer 0 (h = 0)
        uint4 z = make_uint4(0, 0, 0, 0);
        uint4* hz = (uint4*)g_hfrag[0];
        for (int e = gid; e < (1 << 15); e += GSZ) hz[e] = z;
    }
    gridbar0();

    // ---- per-CTA geometry ----
    const int tileM = cta & 3;             // co-resident CTAs share tileM
    const int tileN = cta >> 2;            // 0..63 (32 gate-cols = 8 units)
    const int m16g  = tileM * 8 + wti;

    // copy this CTA's W fragments to smem (once; chunks (kt*4+j), 256B each)
    {
        uint4* s4 = (uint4*)wsm;
        const uint4* g4 = (const uint4*)g_Wfrag;
        for (int e = tid; e < WSMEM_BYTES / 16; e += NTHREADS) {
            int w = e & 15, c = e >> 4;
            int kt = c >> 2, j = c & 3;
            s4[e] = __ldcg(&g4[((((tileN * 4 + j) << 5) + kt) << 4) + w]);
        }
    }
    for (int e = tid; e < 32; e += NTHREADS) {
        int u = e >> 2, g = e & 3;
        int ku = tileN * 8 + u;
        ((float*)sm_wih)[e]  = W_ih[g * HID + ku];
        ((float*)sm_bias)[e] = b_ih[g * HID + ku] + b_hh[g * HID + ku];
    }
    __syncthreads();

    float creg[2][2];                      // [rh][block b]
    creg[0][0] = creg[0][1] = creg[1][0] = creg[1][1] = 0.0f;

    const int row_base = tileM * 128 + wti * 16 + gq;
    const int k16w  = tileN >> 1;          // A-fragment k16 this CTA co-writes
    const int khalf = tileN & 1;           // which 8-byte half of each lane slot

    // ---- recurrent loop ----
    for (int t = 0; t < TLEN; ++t) {
        const unsigned char* hin  = g_hfrag[t & 1];
        unsigned char*       hout = g_hfrag[(t + 1) & 1];
        const unsigned char* abase = hin + ((size_t)(m16g * 32) << 9) + lane * 16;
        const unsigned char* wbase = wsm + lane * 8;

        // prefetch xv (L1-cold after CCTL.IVALL) to overlap with mainloop
        float xv0 = seq[row_base * TLEN + t];
        float xv1 = seq[(row_base + 8) * TLEN + t];

        float acc[4][4];
        #pragma unroll
        for (int j = 0; j < 4; ++j)
            #pragma unroll
            for (int c = 0; c < 4; ++c) acc[j][c] = 0.0f;

        uint4 ah[2];                       // plain LDG -> L1 (fence invalidates)
        ah[0] = *(const uint4*)(abase);
        ah[1] = *(const uint4*)(abase + 512);

        #pragma unroll 2
        for (int kt = 0; kt < 32; ++kt) {
            const int s = kt & 1;
            uint2 bw[4];
            #pragma unroll
            for (int j = 0; j < 4; ++j)
                bw[j] = *(const uint2*)(wbase + (((kt << 2) + j) << 8));
            #pragma unroll
            for (int j = 0; j < 4; ++j) MMA_F16(acc[j], ah[s], bw[j].x, bw[j].y);
            if (kt + 2 < 32)
                ah[s] = *(const uint4*)(abase + ((size_t)(kt + 2) << 9));
        }

        // ---- epilogue: gates -> c,h ; stage h (fp32) ----
        #pragma unroll
        for (int rh = 0; rh < 2; ++rh) {
            float xv = rh ? xv1 : xv0;
            #pragma unroll
            for (int b = 0; b < 2; ++b) {
                float4 wv = sm_wih[b * 4 + tg];
                float4 bv = sm_bias[b * 4 + tg];
                float gi = acc[2*b  ][rh*2+0] + xv * wv.x + bv.x;
                float gf = acc[2*b  ][rh*2+1] + xv * wv.y + bv.y;
                float gg = acc[2*b+1][rh*2+0] + xv * wv.z + bv.z;
                float go = acc[2*b+1][rh*2+1] + xv * wv.w + bv.w;
                float cc = sigf(gf) * creg[rh][b] + sigf(gi) * tanhft(gg);
                creg[rh][b] = cc;
                float hv = sigf(go) * tanhft(cc);
                stage[wti][gq + rh * 8][b * 4 + tg] = hv;
                if (t == TLEN - 1)
                    g_hfin[(row_base + rh * 8) * HID + tileN * 8 + b * 4 + tg] = hv;
            }
        }
        __syncwarp();
        // repack: this CTA supplies k-half 'khalf' of A fragment (m16g, k16w)
        {
            float a0 = stage[wti][gq    ][tg * 2];
            float a1 = stage[wti][gq    ][tg * 2 + 1];
            float b0 = stage[wti][gq + 8][tg * 2];
            float b1 = stage[wti][gq + 8][tg * 2 + 1];
            unsigned int r0 = packh(a0, a1), r1 = packh(b0, b1);
            unsigned char* op = hout + ((size_t)(m16g * 32 + k16w) << 9)
                                     + lane * 16 + khalf * 8;
            *(uint2*)op = make_uint2(r0, r1);
        }

        groupbar(tileM, tileN, (unsigned int)(t + 1), wti, lane);
    }

    // ---- reset barrier flags for next graph replay (after full-grid sync) ----
    gridbar0();
    if (tid == 0)
        *(volatile unsigned int*)&g_aflag[tileM][tileN * 8] = 0u;

    // ---- fc1: hid = relu(h @ fc1w^T + fc1b), 2 batch rows per CTA ----
    const int bb = tileM * 128 + tileN * 2;
    {
        for (int e = tid; e < 2 * HID; e += NTHREADS)
            hs[e >> 9][e & 511] = g_hfin[(bb + (e >> 9)) * HID + (e & 511)];
        __syncthreads();
        int n = tid;                            // HALF == 256 == NTHREADS
        const float* wr = fc1w + n * HID;
        float s0 = fc1b[n], s1 = s0;
        #pragma unroll 8
        for (int k = 0; k < HID; ++k) {
            float w = wr[k];
            s0 += hs[0][k] * w; s1 += hs[1][k] * w;
        }
        sm_hid[0][n] = fmaxf(s0, 0.0f);
        sm_hid[1][n] = fmaxf(s1, 0.0f);
    }
    __syncthreads();

    // ---- fc2 (rows bb, bb+1) ----
    for (int i = tid; i < 2 * TGT; i += NTHREADS) {
        int r  = i / TGT;
        int tt = i - r * TGT;
        const float* hr = sm_hid[r];
        const float* wr = fc2w + tt * HALF;
        float s = fc2b[tt];
        #pragma unroll 8
        for (int k = 0; k < HALF; ++k) s += hr[k] * wr[k];
        out[(bb + r) * TGT + tt] = s;
    }
}

extern "C" void kernel_launch(void* const* d_in, const int* in_sizes, int n_in,
                              void* d_out, int out_size) {
    (void)in_sizes; (void)n_in; (void)out_size;
    cudaFuncSetAttribute(lstm_mma_kernel,
                         cudaFuncAttributeMaxDynamicSharedMemorySize, WSMEM_BYTES);
    lstm_mma_kernel<<<NCTAS, NTHREADS, WSMEM_BYTES>>>(
        (const float*)d_in[0], (const float*)d_in[1], (const float*)d_in[2],
        (const float*)d_in[3], (const float*)d_in[4], (const float*)d_in[5],
        (const float*)d_in[6], (const float*)d_in[7], (const float*)d_in[8],
        (float*)d_out);
}